// round 1
// baseline (speedup 1.0000x reference)
#include <cuda_runtime.h>
#include <cuda_bf16.h>
#include <math_constants.h>

#define B_   16
#define C_   256
#define N_   4096
#define O3_  768
#define HEADS_ 8
#define HD_  32
#define EPS_ 1e-5f

// Scratch (device globals — allocation-free rule)
__device__ float g_qkv[(size_t)B_ * O3_ * N_];   // 192 MB: qkv after BN, q/k softmaxed in place
__device__ float g_ctx[(size_t)B_ * HEADS_ * HD_ * HD_];
__device__ float g_M[(size_t)B_ * C_ * C_];      // folded proj_w @ ctx

// ---------------------------------------------------------------------------
// Unified 128x128x16 SGEMM with per-output-channel BN epilogue.
// C[o,n] = BN( sum_c A[o,c] * Bm[c,n] )   per batch (blockIdx.z)
// A row-major [ODIM,256], Bm row-major [256, 4096].
// ---------------------------------------------------------------------------
__global__ __launch_bounds__(256, 2)
void gemm128_bn(const float* __restrict__ A, long aStride,
                const float* __restrict__ Bm, long bStride,
                float* __restrict__ Out, long oStride,
                const float* __restrict__ gamma, const float* __restrict__ beta,
                const float* __restrict__ mean,  const float* __restrict__ var)
{
    const int b  = blockIdx.z;
    const int n0 = blockIdx.x * 128;
    const int o0 = blockIdx.y * 128;
    const float* Ab = A  + (size_t)b * aStride;
    const float* Bb = Bm + (size_t)b * bStride;
    float*       Ob = Out + (size_t)b * oStride;

    __shared__ float As[16][128];
    __shared__ float Bs[16][128];

    const int t  = threadIdx.x;       // 256 threads
    const int ty = t >> 4;            // 0..15 (o tiles)
    const int tx = t & 15;            // 0..15 (n tiles)

    float acc[8][8];
#pragma unroll
    for (int i = 0; i < 8; i++)
#pragma unroll
        for (int j = 0; j < 8; j++) acc[i][j] = 0.f;

    const int ra = t >> 2;            // 0..63
    const int ca = (t & 3) * 4;       // 0,4,8,12
    const int rb = t >> 5;            // 0..7
    const int cb = (t & 31) * 4;      // 0..124

    for (int k0 = 0; k0 < 256; k0 += 16) {
        // Load A tile (transposed into As[k][o])
#pragma unroll
        for (int rr = 0; rr < 2; rr++) {
            float4 av = *(const float4*)&Ab[(size_t)(o0 + ra + rr * 64) * 256 + k0 + ca];
            As[ca + 0][ra + rr * 64] = av.x;
            As[ca + 1][ra + rr * 64] = av.y;
            As[ca + 2][ra + rr * 64] = av.z;
            As[ca + 3][ra + rr * 64] = av.w;
        }
        // Load B tile
#pragma unroll
        for (int rr = 0; rr < 2; rr++) {
            float4 bv = *(const float4*)&Bb[(size_t)(k0 + rb + rr * 8) * N_ + n0 + cb];
            *(float4*)&Bs[rb + rr * 8][cb] = bv;
        }
        __syncthreads();

#pragma unroll
        for (int kk = 0; kk < 16; kk++) {
            float af[8], bf[8];
            *(float4*)&af[0] = *(const float4*)&As[kk][ty * 8 + 0];
            *(float4*)&af[4] = *(const float4*)&As[kk][ty * 8 + 4];
            *(float4*)&bf[0] = *(const float4*)&Bs[kk][tx * 8 + 0];
            *(float4*)&bf[4] = *(const float4*)&Bs[kk][tx * 8 + 4];
#pragma unroll
            for (int i = 0; i < 8; i++)
#pragma unroll
                for (int j = 0; j < 8; j++)
                    acc[i][j] += af[i] * bf[j];
        }
        __syncthreads();
    }

    // BN epilogue + store
#pragma unroll
    for (int i = 0; i < 8; i++) {
        const int o = o0 + ty * 8 + i;
        const float sc = gamma[o] * rsqrtf(var[o] + EPS_);
        const float sh = beta[o] - mean[o] * sc;
        float4 v0, v1;
        v0.x = acc[i][0] * sc + sh; v0.y = acc[i][1] * sc + sh;
        v0.z = acc[i][2] * sc + sh; v0.w = acc[i][3] * sc + sh;
        v1.x = acc[i][4] * sc + sh; v1.y = acc[i][5] * sc + sh;
        v1.z = acc[i][6] * sc + sh; v1.w = acc[i][7] * sc + sh;
        float* po = &Ob[(size_t)o * N_ + n0 + tx * 8];
        *(float4*)&po[0] = v0;
        *(float4*)&po[4] = v1;
    }
}

// ---------------------------------------------------------------------------
// Block reductions
// ---------------------------------------------------------------------------
__device__ __forceinline__ float blockReduceMax(float v) {
    __shared__ float sm[32];
#pragma unroll
    for (int o = 16; o; o >>= 1) v = fmaxf(v, __shfl_xor_sync(0xffffffffu, v, o));
    if ((threadIdx.x & 31) == 0) sm[threadIdx.x >> 5] = v;
    __syncthreads();
    if (threadIdx.x < 32) {
        float w = (threadIdx.x < (blockDim.x >> 5)) ? sm[threadIdx.x] : -CUDART_INF_F;
#pragma unroll
        for (int o = 16; o; o >>= 1) w = fmaxf(w, __shfl_xor_sync(0xffffffffu, w, o));
        if (threadIdx.x == 0) sm[0] = w;
    }
    __syncthreads();
    float r = sm[0];
    __syncthreads();
    return r;
}

__device__ __forceinline__ float blockReduceSum(float v) {
    __shared__ float sm[32];
#pragma unroll
    for (int o = 16; o; o >>= 1) v += __shfl_xor_sync(0xffffffffu, v, o);
    if ((threadIdx.x & 31) == 0) sm[threadIdx.x >> 5] = v;
    __syncthreads();
    if (threadIdx.x < 32) {
        float w = (threadIdx.x < (blockDim.x >> 5)) ? sm[threadIdx.x] : 0.f;
#pragma unroll
        for (int o = 16; o; o >>= 1) w += __shfl_xor_sync(0xffffffffu, w, o);
        if (threadIdx.x == 0) sm[0] = w;
    }
    __syncthreads();
    float r = sm[0];
    __syncthreads();
    return r;
}

// ---------------------------------------------------------------------------
// q softmax: over n (row of 4096), in place. One block per (b, o<256).
// ---------------------------------------------------------------------------
__global__ __launch_bounds__(256)
void softmax_q()
{
    const int row = blockIdx.x;             // b*256 + o
    const int b = row >> 8;
    const int o = row & 255;
    float* p = g_qkv + (size_t)b * O3_ * N_ + (size_t)o * N_;
    const int t = threadIdx.x;

    float v[16];
#pragma unroll
    for (int i = 0; i < 16; i++) v[i] = p[t + i * 256];

    float m = -CUDART_INF_F;
#pragma unroll
    for (int i = 0; i < 16; i++) m = fmaxf(m, v[i]);
    m = blockReduceMax(m);

    float s = 0.f;
#pragma unroll
    for (int i = 0; i < 16; i++) { v[i] = __expf(v[i] - m); s += v[i]; }
    s = blockReduceSum(s);

    const float inv = 1.f / s;
#pragma unroll
    for (int i = 0; i < 16; i++) p[t + i * 256] = v[i] * inv;
}

// ---------------------------------------------------------------------------
// k softmax: over d (32 values, stride N), per (b,h,n). In place.
// grid (N/256, HEADS, B), block 256
// ---------------------------------------------------------------------------
__global__ __launch_bounds__(256)
void softmax_k()
{
    const int n = blockIdx.x * 256 + threadIdx.x;
    const int h = blockIdx.y;
    const int b = blockIdx.z;
    float* p = g_qkv + (size_t)b * O3_ * N_ + (size_t)(C_ + h * HD_) * N_ + n;

    float v[HD_];
#pragma unroll
    for (int d = 0; d < HD_; d++) v[d] = p[(size_t)d * N_];
    float m = -CUDART_INF_F;
#pragma unroll
    for (int d = 0; d < HD_; d++) m = fmaxf(m, v[d]);
    float s = 0.f;
#pragma unroll
    for (int d = 0; d < HD_; d++) { v[d] = __expf(v[d] - m); s += v[d]; }
    const float inv = 1.f / s;
#pragma unroll
    for (int d = 0; d < HD_; d++) p[(size_t)d * N_] = v[d] * inv;
}

// ---------------------------------------------------------------------------
// ctx[b,h,d,e] = sum_n k[d,n] * v[e,n].  grid (HEADS, B), block 256
// ---------------------------------------------------------------------------
__global__ __launch_bounds__(256)
void ctx_kernel()
{
    const int h = blockIdx.x;
    const int b = blockIdx.y;
    const float* kp = g_qkv + (size_t)b * O3_ * N_ + (size_t)(C_ + h * HD_) * N_;
    const float* vp = g_qkv + (size_t)b * O3_ * N_ + (size_t)(2 * C_ + h * HD_) * N_;

    __shared__ float ks[128][33];
    __shared__ float vs[128][33];

    const int t = threadIdx.x;
    const int i = t >> 4;     // d tile
    const int j = t & 15;     // e tile
    float a00 = 0.f, a01 = 0.f, a10 = 0.f, a11 = 0.f;

    for (int n0 = 0; n0 < N_; n0 += 128) {
#pragma unroll
        for (int s = 0; s < 16; s++) {
            const int l = t + s * 256;
            const int d = l >> 7, nn = l & 127;
            ks[nn][d] = kp[(size_t)d * N_ + n0 + nn];
            vs[nn][d] = vp[(size_t)d * N_ + n0 + nn];
        }
        __syncthreads();
#pragma unroll 8
        for (int kk = 0; kk < 128; kk++) {
            const float k0 = ks[kk][2 * i], k1 = ks[kk][2 * i + 1];
            const float v0 = vs[kk][2 * j], v1 = vs[kk][2 * j + 1];
            a00 += k0 * v0; a01 += k0 * v1;
            a10 += k1 * v0; a11 += k1 * v1;
        }
        __syncthreads();
    }

    float* cp = g_ctx + (size_t)((b * HEADS_ + h) * HD_) * HD_;
    cp[(2 * i + 0) * HD_ + 2 * j + 0] = a00;
    cp[(2 * i + 0) * HD_ + 2 * j + 1] = a01;
    cp[(2 * i + 1) * HD_ + 2 * j + 0] = a10;
    cp[(2 * i + 1) * HD_ + 2 * j + 1] = a11;
}

// ---------------------------------------------------------------------------
// fold: M[b,o,h*32+d] = sum_e proj_w[o,h*32+e] * ctx[b,h,d,e]
// grid (256, B), block 256 (thread = c = h*32+d)
// ---------------------------------------------------------------------------
__global__ __launch_bounds__(256)
void fold_kernel(const float* __restrict__ pw)
{
    const int o = blockIdx.x;
    const int b = blockIdx.y;
    const int c = threadIdx.x;
    const int h = c >> 5, d = c & 31;
    const float* ct = g_ctx + (size_t)((b * HEADS_ + h) * HD_ + d) * HD_;
    const float* wr = pw + (size_t)o * C_ + h * HD_;
    float s = 0.f;
#pragma unroll
    for (int e = 0; e < HD_; e++) s += wr[e] * ct[e];
    g_M[((size_t)b * C_ + o) * C_ + c] = s;
}

// ---------------------------------------------------------------------------
extern "C" void kernel_launch(void* const* d_in, const int* in_sizes, int n_in,
                              void* d_out, int out_size)
{
    const float* x          = (const float*)d_in[0];
    const float* qkv_w      = (const float*)d_in[1];
    const float* qkv_gamma  = (const float*)d_in[2];
    const float* qkv_beta   = (const float*)d_in[3];
    const float* qkv_mean   = (const float*)d_in[4];
    const float* qkv_var    = (const float*)d_in[5];
    const float* proj_w     = (const float*)d_in[6];
    const float* proj_gamma = (const float*)d_in[7];
    const float* proj_beta  = (const float*)d_in[8];
    const float* proj_mean  = (const float*)d_in[9];
    const float* proj_var   = (const float*)d_in[10];
    float* out = (float*)d_out;

    void* p;
    cudaGetSymbolAddress(&p, g_qkv);
    float* qkv = (float*)p;
    cudaGetSymbolAddress(&p, g_M);
    float* Mm = (float*)p;

    // 1) QKV GEMM + BN  -> g_qkv
    gemm128_bn<<<dim3(N_ / 128, O3_ / 128, B_), 256>>>(
        qkv_w, 0, x, (long)C_ * N_, qkv, (long)O3_ * N_,
        qkv_gamma, qkv_beta, qkv_mean, qkv_var);

    // 2) softmaxes in place
    softmax_q<<<B_ * C_, 256>>>();
    softmax_k<<<dim3(N_ / 256, HEADS_, B_), 256>>>();

    // 3) ctx = k @ v^T
    ctx_kernel<<<dim3(HEADS_, B_), 256>>>();

    // 4) fold proj_w with ctx
    fold_kernel<<<dim3(C_, B_), 256>>>(proj_w);

    // 5) out = M @ q  + proj BN
    gemm128_bn<<<dim3(N_ / 128, C_ / 128, B_), 256>>>(
        Mm, (long)C_ * C_, qkv, (long)O3_ * N_, out, (long)C_ * N_,
        proj_gamma, proj_beta, proj_mean, proj_var);
}

// round 2
// speedup vs baseline: 1.1573x; 1.1573x over previous
#include <cuda_runtime.h>
#include <cuda_bf16.h>
#include <math_constants.h>

#define B_   16
#define C_   256
#define N_   4096
#define O3_  768
#define HEADS_ 8
#define HD_  32
#define EPS_ 1e-5f

// Scratch (device globals — allocation-free rule)
__device__ float g_qkv[(size_t)B_ * O3_ * N_];   // qkv after BN; q softmaxed in place
__device__ float g_ctx[(size_t)B_ * HEADS_ * HD_ * HD_];
__device__ float g_M[(size_t)B_ * C_ * C_];      // folded proj_w @ ctx

// ---------------------------------------------------------------------------
// Unified 128x128x16 SGEMM with per-output-channel BN epilogue.
// C[o,n] = BN( sum_c A[o,c] * Bm[c,n] )   per batch (blockIdx.z)
// ---------------------------------------------------------------------------
__global__ __launch_bounds__(256, 2)
void gemm128_bn(const float* __restrict__ A, long aStride,
                const float* __restrict__ Bm, long bStride,
                float* __restrict__ Out, long oStride,
                const float* __restrict__ gamma, const float* __restrict__ beta,
                const float* __restrict__ mean,  const float* __restrict__ var)
{
    const int b  = blockIdx.z;
    const int n0 = blockIdx.x * 128;
    const int o0 = blockIdx.y * 128;
    const float* Ab = A  + (size_t)b * aStride;
    const float* Bb = Bm + (size_t)b * bStride;
    float*       Ob = Out + (size_t)b * oStride;

    __shared__ float As[16][128];
    __shared__ float Bs[16][128];

    const int t  = threadIdx.x;       // 256 threads
    const int ty = t >> 4;            // 0..15 (o tiles)
    const int tx = t & 15;            // 0..15 (n tiles)

    float acc[8][8];
#pragma unroll
    for (int i = 0; i < 8; i++)
#pragma unroll
        for (int j = 0; j < 8; j++) acc[i][j] = 0.f;

    const int ra = t >> 2;            // 0..63
    const int ca = (t & 3) * 4;       // 0,4,8,12
    const int rb = t >> 5;            // 0..7
    const int cb = (t & 31) * 4;      // 0..124

    for (int k0 = 0; k0 < 256; k0 += 16) {
#pragma unroll
        for (int rr = 0; rr < 2; rr++) {
            float4 av = *(const float4*)&Ab[(size_t)(o0 + ra + rr * 64) * 256 + k0 + ca];
            As[ca + 0][ra + rr * 64] = av.x;
            As[ca + 1][ra + rr * 64] = av.y;
            As[ca + 2][ra + rr * 64] = av.z;
            As[ca + 3][ra + rr * 64] = av.w;
        }
#pragma unroll
        for (int rr = 0; rr < 2; rr++) {
            float4 bv = *(const float4*)&Bb[(size_t)(k0 + rb + rr * 8) * N_ + n0 + cb];
            *(float4*)&Bs[rb + rr * 8][cb] = bv;
        }
        __syncthreads();

#pragma unroll
        for (int kk = 0; kk < 16; kk++) {
            float af[8], bf[8];
            *(float4*)&af[0] = *(const float4*)&As[kk][ty * 8 + 0];
            *(float4*)&af[4] = *(const float4*)&As[kk][ty * 8 + 4];
            *(float4*)&bf[0] = *(const float4*)&Bs[kk][tx * 8 + 0];
            *(float4*)&bf[4] = *(const float4*)&Bs[kk][tx * 8 + 4];
#pragma unroll
            for (int i = 0; i < 8; i++)
#pragma unroll
                for (int j = 0; j < 8; j++)
                    acc[i][j] += af[i] * bf[j];
        }
        __syncthreads();
    }

#pragma unroll
    for (int i = 0; i < 8; i++) {
        const int o = o0 + ty * 8 + i;
        const float sc = gamma[o] * rsqrtf(var[o] + EPS_);
        const float sh = beta[o] - mean[o] * sc;
        float4 v0, v1;
        v0.x = acc[i][0] * sc + sh; v0.y = acc[i][1] * sc + sh;
        v0.z = acc[i][2] * sc + sh; v0.w = acc[i][3] * sc + sh;
        v1.x = acc[i][4] * sc + sh; v1.y = acc[i][5] * sc + sh;
        v1.z = acc[i][6] * sc + sh; v1.w = acc[i][7] * sc + sh;
        float* po = &Ob[(size_t)o * N_ + n0 + tx * 8];
        *(float4*)&po[0] = v0;
        *(float4*)&po[4] = v1;
    }
}

// ---------------------------------------------------------------------------
// Block reductions
// ---------------------------------------------------------------------------
__device__ __forceinline__ float blockReduceMax(float v) {
    __shared__ float sm[32];
#pragma unroll
    for (int o = 16; o; o >>= 1) v = fmaxf(v, __shfl_xor_sync(0xffffffffu, v, o));
    if ((threadIdx.x & 31) == 0) sm[threadIdx.x >> 5] = v;
    __syncthreads();
    if (threadIdx.x < 32) {
        float w = (threadIdx.x < (blockDim.x >> 5)) ? sm[threadIdx.x] : -CUDART_INF_F;
#pragma unroll
        for (int o = 16; o; o >>= 1) w = fmaxf(w, __shfl_xor_sync(0xffffffffu, w, o));
        if (threadIdx.x == 0) sm[0] = w;
    }
    __syncthreads();
    float r = sm[0];
    __syncthreads();
    return r;
}

__device__ __forceinline__ float blockReduceSum(float v) {
    __shared__ float sm[32];
#pragma unroll
    for (int o = 16; o; o >>= 1) v += __shfl_xor_sync(0xffffffffu, v, o);
    if ((threadIdx.x & 31) == 0) sm[threadIdx.x >> 5] = v;
    __syncthreads();
    if (threadIdx.x < 32) {
        float w = (threadIdx.x < (blockDim.x >> 5)) ? sm[threadIdx.x] : 0.f;
#pragma unroll
        for (int o = 16; o; o >>= 1) w += __shfl_xor_sync(0xffffffffu, w, o);
        if (threadIdx.x == 0) sm[0] = w;
    }
    __syncthreads();
    float r = sm[0];
    __syncthreads();
    return r;
}

// ---------------------------------------------------------------------------
// q softmax: over n (row of 4096), in place. One block per (b, o<256).
// ---------------------------------------------------------------------------
__global__ __launch_bounds__(256)
void softmax_q()
{
    const int row = blockIdx.x;             // b*256 + o
    const int b = row >> 8;
    const int o = row & 255;
    float* p = g_qkv + (size_t)b * O3_ * N_ + (size_t)o * N_;
    const int t = threadIdx.x;

    float v[16];
#pragma unroll
    for (int i = 0; i < 16; i++) v[i] = p[t + i * 256];

    float m = -CUDART_INF_F;
#pragma unroll
    for (int i = 0; i < 16; i++) m = fmaxf(m, v[i]);
    m = blockReduceMax(m);

    float s = 0.f;
#pragma unroll
    for (int i = 0; i < 16; i++) { v[i] = __expf(v[i] - m); s += v[i]; }
    s = blockReduceSum(s);

    const float inv = 1.f / s;
#pragma unroll
    for (int i = 0; i < 16; i++) p[t + i * 256] = v[i] * inv;
}

// ---------------------------------------------------------------------------
// ctx split-N with fused k-softmax:
//   ctx[b,h,d,e] += sum_{n in split} softmax_d(k)[d,n] * v[e,n]
// grid (HEADS, B, 16 splits of 256 tokens), block 256.
// g_ctx must be zeroed before launch.
// ---------------------------------------------------------------------------
__global__ __launch_bounds__(256)
void ctx_kernel()
{
    const int h = blockIdx.x;
    const int b = blockIdx.y;
    const int n0b = blockIdx.z * 256;
    const float* kp = g_qkv + (size_t)b * O3_ * N_ + (size_t)(C_ + h * HD_) * N_;
    const float* vp = g_qkv + (size_t)b * O3_ * N_ + (size_t)(2 * C_ + h * HD_) * N_;

    __shared__ float ks[128][33];
    __shared__ float vs[128][33];

    const int t = threadIdx.x;
    const int i = t >> 4;     // d tile (0..15)
    const int j = t & 15;     // e tile (0..15)
    float a00 = 0.f, a01 = 0.f, a10 = 0.f, a11 = 0.f;

    for (int cchunk = 0; cchunk < 2; cchunk++) {
        const int n0 = n0b + cchunk * 128;
        // Coalesced tile load (raw k, raw v)
#pragma unroll
        for (int s = 0; s < 16; s++) {
            const int l = t + s * 256;
            const int d = l >> 7, nn = l & 127;
            ks[nn][d] = kp[(size_t)d * N_ + n0 + nn];
            vs[nn][d] = vp[(size_t)d * N_ + n0 + nn];
        }
        __syncthreads();

        // Fused k-softmax over d (32 values) per token column nn.
        // Row stride 33 -> conflict-free across threads for fixed d.
        if (t < 128) {
            float m = -CUDART_INF_F;
#pragma unroll
            for (int d = 0; d < HD_; d++) m = fmaxf(m, ks[t][d]);
            float s = 0.f;
#pragma unroll
            for (int d = 0; d < HD_; d++) { float e = __expf(ks[t][d] - m); ks[t][d] = e; s += e; }
            const float inv = 1.f / s;
#pragma unroll
            for (int d = 0; d < HD_; d++) ks[t][d] *= inv;
        }
        __syncthreads();

#pragma unroll 8
        for (int kk = 0; kk < 128; kk++) {
            const float k0 = ks[kk][2 * i], k1 = ks[kk][2 * i + 1];
            const float v0 = vs[kk][2 * j], v1 = vs[kk][2 * j + 1];
            a00 += k0 * v0; a01 += k0 * v1;
            a10 += k1 * v0; a11 += k1 * v1;
        }
        __syncthreads();
    }

    float* cp = g_ctx + (size_t)((b * HEADS_ + h) * HD_) * HD_;
    atomicAdd(&cp[(2 * i + 0) * HD_ + 2 * j + 0], a00);
    atomicAdd(&cp[(2 * i + 0) * HD_ + 2 * j + 1], a01);
    atomicAdd(&cp[(2 * i + 1) * HD_ + 2 * j + 0], a10);
    atomicAdd(&cp[(2 * i + 1) * HD_ + 2 * j + 1], a11);
}

// ---------------------------------------------------------------------------
// fold: M[b,o,h*32+d] = sum_e proj_w[o,h*32+e] * ctx[b,h,d,e]
// ---------------------------------------------------------------------------
__global__ __launch_bounds__(256)
void fold_kernel(const float* __restrict__ pw)
{
    const int o = blockIdx.x;
    const int b = blockIdx.y;
    const int c = threadIdx.x;
    const int h = c >> 5, d = c & 31;
    const float* ct = g_ctx + (size_t)((b * HEADS_ + h) * HD_ + d) * HD_;
    const float* wr = pw + (size_t)o * C_ + h * HD_;
    float s = 0.f;
#pragma unroll
    for (int e = 0; e < HD_; e++) s += wr[e] * ct[e];
    g_M[((size_t)b * C_ + o) * C_ + c] = s;
}

// ---------------------------------------------------------------------------
extern "C" void kernel_launch(void* const* d_in, const int* in_sizes, int n_in,
                              void* d_out, int out_size)
{
    const float* x          = (const float*)d_in[0];
    const float* qkv_w      = (const float*)d_in[1];
    const float* qkv_gamma  = (const float*)d_in[2];
    const float* qkv_beta   = (const float*)d_in[3];
    const float* qkv_mean   = (const float*)d_in[4];
    const float* qkv_var    = (const float*)d_in[5];
    const float* proj_w     = (const float*)d_in[6];
    const float* proj_gamma = (const float*)d_in[7];
    const float* proj_beta  = (const float*)d_in[8];
    const float* proj_mean  = (const float*)d_in[9];
    const float* proj_var   = (const float*)d_in[10];
    float* out = (float*)d_out;

    void* p;
    cudaGetSymbolAddress(&p, g_qkv);
    float* qkv = (float*)p;
    cudaGetSymbolAddress(&p, g_M);
    float* Mm = (float*)p;
    void* ctxp;
    cudaGetSymbolAddress(&ctxp, g_ctx);

    // 1) QKV GEMM + BN  -> g_qkv
    gemm128_bn<<<dim3(N_ / 128, O3_ / 128, B_), 256>>>(
        qkv_w, 0, x, (long)C_ * N_, qkv, (long)O3_ * N_,
        qkv_gamma, qkv_beta, qkv_mean, qkv_var);

    // 2) q softmax in place; zero ctx accumulator
    softmax_q<<<B_ * C_, 256>>>();
    cudaMemsetAsync(ctxp, 0, sizeof(float) * B_ * HEADS_ * HD_ * HD_);

    // 3) ctx = softmax_d(k) @ v^T  (split-N, fused k-softmax, atomic reduce)
    ctx_kernel<<<dim3(HEADS_, B_, 16), 256>>>();

    // 4) fold proj_w with ctx
    fold_kernel<<<dim3(C_, B_), 256>>>(proj_w);

    // 5) out = M @ q  + proj BN
    gemm128_bn<<<dim3(N_ / 128, C_ / 128, B_), 256>>>(
        Mm, (long)C_ * C_, qkv, (long)O3_ * N_, out, (long)C_ * N_,
        proj_gamma, proj_beta, proj_mean, proj_var);
}